// round 14
// baseline (speedup 1.0000x reference)
#include <cuda_runtime.h>
#include <math.h>

#define HH 32
#define WW 40
#define SS 1280
#define NH 8
#define HD 32
#define CAP 384
#define QS 256   // NH*HD

// ---- strict IEEE fp32 helpers (no compiler contraction possible) ----
#define FMUL(a,b)    __fmul_rn((a),(b))
#define FADD(a,b)    __fadd_rn((a),(b))
#define FSUB(a,b)    __fsub_rn((a),(b))
#define FDIV(a,b)    __fdiv_rn((a),(b))

__device__ __forceinline__ float ex2(float x) {
    float r;
    asm("ex2.approx.f32 %0, %1;" : "=f"(r) : "f"(x));
    return r;
}

// 3x3 fp32 matmul: multiply then reduce-add, NO fma, k ascending
// (bit-exact match to the reference pipeline — do not modify).
__device__ __forceinline__ void mm3(const float A[9], const float B[9], float C[9]) {
    #pragma unroll
    for (int i = 0; i < 3; i++)
        #pragma unroll
        for (int j = 0; j < 3; j++) {
            float p0 = FMUL(A[i*3+0], B[0*3+j]);
            float p1 = FMUL(A[i*3+1], B[1*3+j]);
            float p2 = FMUL(A[i*3+2], B[2*3+j]);
            C[i*3+j] = FADD(FADD(p0, p1), p2);
        }
}

__global__ __launch_bounds__(256, 5)
void one2many_attn_kernel(
    const float* __restrict__ q, const float* __restrict__ k, const float* __restrict__ v,
    const float* __restrict__ K0, const float* __restrict__ K1,
    const float* __restrict__ R,  const float* __restrict__ t,
    float* __restrict__ out)
{
    __shared__ float qsA[QS], qsB[QS];
    __shared__ __align__(16) int cand[CAP + 16];  // (s*256) | flagA | flagB<<1
    __shared__ int   cnt;
    __shared__ float geo[4];                 // slopeA, iceptA, slopeB, iceptB
    __shared__ int   gmode[2];

    const int pr  = blockIdx.x;
    const int lA  = 2*pr, lB = 2*pr + 1;     // same row (WW even)
    const int tid = threadIdx.x;
    const int lane = tid & 31;

    // ---- inline geometry (bit-exact; F computed once, two line evals)
    if (tid == 0) {
        auto inv_ut = [](const float* K, float ik[9]) {
            float i00 = FDIV(1.0f, K[0]);
            float i11 = FDIV(1.0f, K[4]);
            float i22 = FDIV(1.0f, K[8]);
            float x1  = FDIV(FMUL(-K[5], i22), K[4]);
            float x0  = FDIV(FMUL(-K[2], i22), K[0]);
            ik[0]=i00; ik[1]=0.f; ik[2]=x0;
            ik[3]=0.f; ik[4]=i11; ik[5]=x1;
            ik[6]=0.f; ik[7]=0.f; ik[8]=i22;
        };
        float ik0[9], ik1[9], rr[9];
        inv_ut(K0, ik0);
        inv_ut(K1, ik1);
        #pragma unroll
        for (int i = 0; i < 9; i++) rr[i] = R[i];

        const float t0 = t[0], t1 = t[1], t2 = t[2];
        const float sk[9] = { 0.f, -t2,  t1,
                              t2,  0.f, -t0,
                             -t1,  t0,  0.f };
        float ik1T[9];
        #pragma unroll
        for (int i = 0; i < 3; i++)
            #pragma unroll
            for (int j = 0; j < 3; j++) ik1T[i*3+j] = ik1[j*3+i];

        float T1[9], T2[9], F[9];
        mm3(ik1T, sk, T1);
        mm3(T1, rr, T2);
        mm3(T2, ik0, F);

        #pragma unroll
        for (int e = 0; e < 2; e++) {
            const int l = lA + e;
            const float x = (float)(l % WW), y = (float)(l / WW);
            float a = FADD(FADD(FMUL(F[0], x), FMUL(F[1], y)), F[2]);
            float b = FADD(FADD(FMUL(F[3], x), FMUL(F[4], y)), F[5]);
            float c = FADD(FADD(FMUL(F[6], x), FMUL(F[7], y)), F[8]);
            const bool mode = fabsf(b) > fabsf(a);
            const float denom = mode ? b : a;
            geo[2*e+0] = FDIV(-(mode ? a : b), denom);
            geo[2*e+1] = FDIV(-c, denom);
            gmode[e]   = mode ? 1 : 0;
        }
        cnt = 0;
    }
    // q pre-scaled by 1/sqrt(32)*log2(e): dots feed ex2 directly.
    const float QSCALE = 0.25505393f;   // 0.17677669529663687 * 1.4426950408889634
    qsA[tid] = q[(size_t)lA * QS + tid] * QSCALE;
    qsB[tid] = q[(size_t)lB * QS + tid] * QSCALE;
    __syncthreads();

    const float slopeA = geo[0], iceptA = geo[1];
    const float slopeB = geo[2], iceptB = geo[3];
    const bool  modeA  = gmode[0] != 0, modeB = gmode[1] != 0;

    // ---- candidate enumeration with per-query membership flags.
    // Comparisons are the EXACT strict-fp32 tests of the reference pipeline
    // for each query independently -> identical membership bits.
    if (modeA == modeB) {
        const bool mode = modeA;
        const int indepN = mode ? WW : HH;
        const int depmax = mode ? HH : WW;
        if (tid < indepN) {
            float fi = (float)tid;
            float cvA = FADD(FMUL(slopeA, fi), iceptA);
            float hiA = FADD(cvA, 2.0f), loA = FSUB(cvA, 2.0f);
            float cvB = FADD(FMUL(slopeB, fi), iceptB);
            float hiB = FADD(cvB, 2.0f), loB = FSUB(cvB, 2.0f);
            int d0 = (int)floorf(fminf(loA, loB)); if (d0 < 0) d0 = 0;
            int d1 = (int)ceilf (fmaxf(hiA, hiB)); if (d1 > depmax-1) d1 = depmax-1;
            int hits[12]; int nh = 0;
            for (int d = d0; d <= d1 && nh < 12; d++) {
                float fd = (float)d;
                int fl = ((fd < hiA && fd > loA) ? 1 : 0)
                       | ((fd < hiB && fd > loB) ? 2 : 0);
                int s = mode ? d*WW + tid : tid*WW + d;
                if (fl && s) hits[nh++] = (s << 8) | fl;
            }
            if (nh) {
                int p = atomicAdd(&cnt, nh);
                for (int j = 0; j < nh; j++)
                    if (p + j < CAP) cand[p + j] = hits[j];
            }
        }
    } else {
        // rare fallback: append each query's set separately (no dedup; exact)
        #pragma unroll
        for (int e = 0; e < 2; e++) {
            const float slope = (e == 0) ? slopeA : slopeB;
            const float icept = (e == 0) ? iceptA : iceptB;
            const bool  mode  = (e == 0) ? modeA  : modeB;
            const int indepN = mode ? WW : HH;
            const int depmax = mode ? HH : WW;
            if (tid < indepN) {
                float fi = (float)tid;
                float cv = FADD(FMUL(slope, fi), icept);
                float hi = FADD(cv, 2.0f), lo = FSUB(cv, 2.0f);
                int d0 = (int)floorf(lo); if (d0 < 0) d0 = 0;
                int d1 = (int)ceilf(hi);  if (d1 > depmax-1) d1 = depmax-1;
                int hits[6]; int nh = 0;
                for (int d = d0; d <= d1 && nh < 6; d++) {
                    float fd = (float)d;
                    if (fd < hi && fd > lo) {
                        int s = mode ? d*WW + tid : tid*WW + d;
                        if (s) hits[nh++] = (s << 8) | (1 << e);
                    }
                }
                if (nh) {
                    int p = atomicAdd(&cnt, nh);
                    for (int j = 0; j < nh; j++)
                        if (p + j < CAP) cand[p + j] = hits[j];
                }
            }
        }
    }
    __syncthreads();

    const int m = min(cnt, CAP);
    // pad 16 null entries (offset 0, flags 0): exact-zero contributions.
    // 16 (not 8) so the pipelined prefetch can read one iteration past m8.
    if (tid < 16) cand[m + tid] = 0;
    __syncthreads();

    const int h = tid >> 5;
    const int hoff = h * HD;

    // ---- Fused pass, software-pipelined: prefetch next iteration's cand+K
    // before executing this iteration's reduce/exp/accum chain.
    // 8 lanes/candidate; cg group handles contiguous pair {2cg, 2cg+1}.
    // Split-reduce: low half-lanes carry query A, high half carry query B.
    const int sub = lane & 7;
    const int cg  = lane >> 3;
    const bool loH = (lane & 4) == 0;
    const float4 q4A = ((const float4*)qsA)[h*8 + sub];
    const float4 q4B = ((const float4*)qsB)[h*8 + sub];
    const float* kh = k + hoff + sub*4;
    const float* vh = v + hoff + sub*4;

    float sumA = 0.f, sumB = 0.f;
    float4 aA = make_float4(0.f,0.f,0.f,0.f);
    float4 aB = make_float4(0.f,0.f,0.f,0.f);

    const int m8 = (m + 7) & ~7;
    int2 ci = *(const int2*)&cand[2*cg];
    float4 k1 = *(const float4*)(kh + (ci.x & ~255));
    float4 k2 = *(const float4*)(kh + (ci.y & ~255));

    for (int c0 = 0; c0 < m8; c0 += 8) {
        const int o1 = ci.x & ~255, f1 = ci.x & 3;
        const int o2 = ci.y & ~255, f2 = ci.y & 3;
        float4 v1 = *(const float4*)(vh + o1);
        float4 v2 = *(const float4*)(vh + o2);
        // prefetch next iteration (reads null pad on the last trip)
        int2 ci_n = *(const int2*)&cand[c0 + 8 + 2*cg];
        float4 k1n = *(const float4*)(kh + (ci_n.x & ~255));
        float4 k2n = *(const float4*)(kh + (ci_n.y & ~255));

        float d1A = k1.x*q4A.x + k1.y*q4A.y + k1.z*q4A.z + k1.w*q4A.w;
        float d1B = k1.x*q4B.x + k1.y*q4B.y + k1.z*q4B.z + k1.w*q4B.w;
        float d2A = k2.x*q4A.x + k2.y*q4A.y + k2.z*q4A.z + k2.w*q4A.w;
        float d2B = k2.x*q4B.x + k2.y*q4B.y + k2.z*q4B.z + k2.w*q4B.w;
        // fold opposite-query halves via xor4, then 2-level reduce (both
        // queries simultaneously: low lanes sum A, high lanes sum B)
        float r1 = (loH ? d1A : d1B) + __shfl_xor_sync(0xffffffffu, loH ? d1B : d1A, 4);
        float r2 = (loH ? d2A : d2B) + __shfl_xor_sync(0xffffffffu, loH ? d2B : d2A, 4);
        r1 += __shfl_xor_sync(0xffffffffu, r1, 1);
        r2 += __shfl_xor_sync(0xffffffffu, r2, 1);
        r1 += __shfl_xor_sync(0xffffffffu, r1, 2);
        r2 += __shfl_xor_sync(0xffffffffu, r2, 2);
        // one exp per chain: low lanes produce eA, high lanes eB
        const bool ok1 = loH ? (f1 & 1) : (f1 & 2);
        const bool ok2 = loH ? (f2 & 1) : (f2 & 2);
        float e1 = ok1 ? ex2(r1) : 0.f;
        float e2 = ok2 ? ex2(r2) : 0.f;
        // broadcast the opposite half's e
        float e1o = __shfl_xor_sync(0xffffffffu, e1, 4);
        float e2o = __shfl_xor_sync(0xffffffffu, e2, 4);
        float e1A = loH ? e1 : e1o,  e1B = loH ? e1o : e1;
        float e2A = loH ? e2 : e2o,  e2B = loH ? e2o : e2;
        sumA += e1A + e2A;
        sumB += e1B + e2B;
        aA.x += e1A*v1.x + e2A*v2.x;  aB.x += e1B*v1.x + e2B*v2.x;
        aA.y += e1A*v1.y + e2A*v2.y;  aB.y += e1B*v1.y + e2B*v2.y;
        aA.z += e1A*v1.z + e2A*v2.z;  aB.z += e1B*v1.z + e2B*v2.z;
        aA.w += e1A*v1.w + e2A*v2.w;  aB.w += e1B*v1.w + e2B*v2.w;

        ci = ci_n; k1 = k1n; k2 = k2n;
    }

    // reduce across the 4 cg groups (disjoint candidate subsets)
    #pragma unroll
    for (int o = 8; o <= 16; o <<= 1) {
        sumA += __shfl_xor_sync(0xffffffffu, sumA, o);
        sumB += __shfl_xor_sync(0xffffffffu, sumB, o);
        aA.x += __shfl_xor_sync(0xffffffffu, aA.x, o);
        aA.y += __shfl_xor_sync(0xffffffffu, aA.y, o);
        aA.z += __shfl_xor_sync(0xffffffffu, aA.z, o);
        aA.w += __shfl_xor_sync(0xffffffffu, aA.w, o);
        aB.x += __shfl_xor_sync(0xffffffffu, aB.x, o);
        aB.y += __shfl_xor_sync(0xffffffffu, aB.y, o);
        aB.z += __shfl_xor_sync(0xffffffffu, aB.z, o);
        aB.w += __shfl_xor_sync(0xffffffffu, aB.w, o);
    }

    const float invA = (sumA > 0.f) ? (1.f / sumA) : 0.f;
    const float invB = (sumB > 0.f) ? (1.f / sumB) : 0.f;
    if (cg == 0) {
        float4 o4 = make_float4(aA.x*invA, aA.y*invA, aA.z*invA, aA.w*invA);
        *(float4*)(out + (size_t)lA*QS + hoff + sub*4) = o4;
    } else if (cg == 1) {
        float4 o4 = make_float4(aB.x*invB, aB.y*invB, aB.z*invB, aB.w*invB);
        *(float4*)(out + (size_t)lB*QS + hoff + sub*4) = o4;
    }
}

extern "C" void kernel_launch(void* const* d_in, const int* in_sizes, int n_in,
                              void* d_out, int out_size) {
    const float* q  = (const float*)d_in[0];
    const float* k  = (const float*)d_in[1];
    const float* v  = (const float*)d_in[2];
    const float* K0 = (const float*)d_in[3];
    const float* K1 = (const float*)d_in[4];
    const float* R  = (const float*)d_in[5];
    const float* t  = (const float*)d_in[6];
    float* out = (float*)d_out;
    one2many_attn_kernel<<<SS/2, 256>>>(q, k, v, K0, K1, R, t, out);
}

// round 15
// speedup vs baseline: 1.0191x; 1.0191x over previous
#include <cuda_runtime.h>
#include <math.h>

#define HH 32
#define WW 40
#define SS 1280
#define NH 8
#define HD 32
#define CAP 384
#define QS 256   // NH*HD

// ---- strict IEEE fp32 helpers (no compiler contraction possible) ----
#define FMUL(a,b)    __fmul_rn((a),(b))
#define FADD(a,b)    __fadd_rn((a),(b))
#define FSUB(a,b)    __fsub_rn((a),(b))
#define FDIV(a,b)    __fdiv_rn((a),(b))

__device__ __forceinline__ float ex2(float x) {
    float r;
    asm("ex2.approx.f32 %0, %1;" : "=f"(r) : "f"(x));
    return r;
}

// 3x3 fp32 matmul: multiply then reduce-add, NO fma, k ascending
// (bit-exact match to the reference pipeline — do not modify).
__device__ __forceinline__ void mm3(const float A[9], const float B[9], float C[9]) {
    #pragma unroll
    for (int i = 0; i < 3; i++)
        #pragma unroll
        for (int j = 0; j < 3; j++) {
            float p0 = FMUL(A[i*3+0], B[0*3+j]);
            float p1 = FMUL(A[i*3+1], B[1*3+j]);
            float p2 = FMUL(A[i*3+2], B[2*3+j]);
            C[i*3+j] = FADD(FADD(p0, p1), p2);
        }
}

__global__ __launch_bounds__(256, 5)
void one2many_attn_kernel(
    const float* __restrict__ q, const float* __restrict__ k, const float* __restrict__ v,
    const float* __restrict__ K0, const float* __restrict__ K1,
    const float* __restrict__ R,  const float* __restrict__ t,
    float* __restrict__ out)
{
    __shared__ float qsA[QS], qsB[QS];
    __shared__ __align__(16) int cand[CAP + 16];  // (s*256) | flagA | flagB<<1
    __shared__ int   cnt;
    __shared__ float geo[4];                 // slopeA, iceptA, slopeB, iceptB
    __shared__ int   gmode[2];

    const int pr  = blockIdx.x;
    const int lA  = 2*pr, lB = 2*pr + 1;     // same row (WW even)
    const int tid = threadIdx.x;
    const int lane = tid & 31;

    // ---- inline geometry (bit-exact; F computed once, two line evals)
    if (tid == 0) {
        auto inv_ut = [](const float* K, float ik[9]) {
            float i00 = FDIV(1.0f, K[0]);
            float i11 = FDIV(1.0f, K[4]);
            float i22 = FDIV(1.0f, K[8]);
            float x1  = FDIV(FMUL(-K[5], i22), K[4]);
            float x0  = FDIV(FMUL(-K[2], i22), K[0]);
            ik[0]=i00; ik[1]=0.f; ik[2]=x0;
            ik[3]=0.f; ik[4]=i11; ik[5]=x1;
            ik[6]=0.f; ik[7]=0.f; ik[8]=i22;
        };
        float ik0[9], ik1[9], rr[9];
        inv_ut(K0, ik0);
        inv_ut(K1, ik1);
        #pragma unroll
        for (int i = 0; i < 9; i++) rr[i] = R[i];

        const float t0 = t[0], t1 = t[1], t2 = t[2];
        const float sk[9] = { 0.f, -t2,  t1,
                              t2,  0.f, -t0,
                             -t1,  t0,  0.f };
        float ik1T[9];
        #pragma unroll
        for (int i = 0; i < 3; i++)
            #pragma unroll
            for (int j = 0; j < 3; j++) ik1T[i*3+j] = ik1[j*3+i];

        float T1[9], T2[9], F[9];
        mm3(ik1T, sk, T1);
        mm3(T1, rr, T2);
        mm3(T2, ik0, F);

        #pragma unroll
        for (int e = 0; e < 2; e++) {
            const int l = lA + e;
            const float x = (float)(l % WW), y = (float)(l / WW);
            float a = FADD(FADD(FMUL(F[0], x), FMUL(F[1], y)), F[2]);
            float b = FADD(FADD(FMUL(F[3], x), FMUL(F[4], y)), F[5]);
            float c = FADD(FADD(FMUL(F[6], x), FMUL(F[7], y)), F[8]);
            const bool mode = fabsf(b) > fabsf(a);
            const float denom = mode ? b : a;
            geo[2*e+0] = FDIV(-(mode ? a : b), denom);
            geo[2*e+1] = FDIV(-c, denom);
            gmode[e]   = mode ? 1 : 0;
        }
        cnt = 0;
    }
    // q pre-scaled by 1/sqrt(32)*log2(e): dots feed ex2 directly.
    const float QSCALE = 0.25505393f;   // 0.17677669529663687 * 1.4426950408889634
    qsA[tid] = q[(size_t)lA * QS + tid] * QSCALE;
    qsB[tid] = q[(size_t)lB * QS + tid] * QSCALE;
    __syncthreads();

    const float slopeA = geo[0], iceptA = geo[1];
    const float slopeB = geo[2], iceptB = geo[3];
    const bool  modeA  = gmode[0] != 0, modeB = gmode[1] != 0;

    // ---- candidate enumeration with per-query membership flags.
    // Comparisons are the EXACT strict-fp32 tests of the reference pipeline
    // for each query independently -> identical membership bits.
    if (modeA == modeB) {
        const bool mode = modeA;
        const int indepN = mode ? WW : HH;
        const int depmax = mode ? HH : WW;
        if (tid < indepN) {
            float fi = (float)tid;
            float cvA = FADD(FMUL(slopeA, fi), iceptA);
            float hiA = FADD(cvA, 2.0f), loA = FSUB(cvA, 2.0f);
            float cvB = FADD(FMUL(slopeB, fi), iceptB);
            float hiB = FADD(cvB, 2.0f), loB = FSUB(cvB, 2.0f);
            int d0 = (int)floorf(fminf(loA, loB)); if (d0 < 0) d0 = 0;
            int d1 = (int)ceilf (fmaxf(hiA, hiB)); if (d1 > depmax-1) d1 = depmax-1;
            int hits[12]; int nh = 0;
            for (int d = d0; d <= d1 && nh < 12; d++) {
                float fd = (float)d;
                int fl = ((fd < hiA && fd > loA) ? 1 : 0)
                       | ((fd < hiB && fd > loB) ? 2 : 0);
                int s = mode ? d*WW + tid : tid*WW + d;
                if (fl && s) hits[nh++] = (s << 8) | fl;
            }
            if (nh) {
                int p = atomicAdd(&cnt, nh);
                for (int j = 0; j < nh; j++)
                    if (p + j < CAP) cand[p + j] = hits[j];
            }
        }
    } else {
        // rare fallback: append each query's set separately (no dedup; exact)
        #pragma unroll
        for (int e = 0; e < 2; e++) {
            const float slope = (e == 0) ? slopeA : slopeB;
            const float icept = (e == 0) ? iceptA : iceptB;
            const bool  mode  = (e == 0) ? modeA  : modeB;
            const int indepN = mode ? WW : HH;
            const int depmax = mode ? HH : WW;
            if (tid < indepN) {
                float fi = (float)tid;
                float cv = FADD(FMUL(slope, fi), icept);
                float hi = FADD(cv, 2.0f), lo = FSUB(cv, 2.0f);
                int d0 = (int)floorf(lo); if (d0 < 0) d0 = 0;
                int d1 = (int)ceilf(hi);  if (d1 > depmax-1) d1 = depmax-1;
                int hits[6]; int nh = 0;
                for (int d = d0; d <= d1 && nh < 6; d++) {
                    float fd = (float)d;
                    if (fd < hi && fd > lo) {
                        int s = mode ? d*WW + tid : tid*WW + d;
                        if (s) hits[nh++] = (s << 8) | (1 << e);
                    }
                }
                if (nh) {
                    int p = atomicAdd(&cnt, nh);
                    for (int j = 0; j < nh; j++)
                        if (p + j < CAP) cand[p + j] = hits[j];
                }
            }
        }
    }
    __syncthreads();

    const int m = min(cnt, CAP);
    // pad 16 null entries (offset 0, flags 0): exact-zero contributions ->
    // the unrolled bulk loop needs no tail or masking.
    if (tid < 16) cand[m + tid] = 0;
    __syncthreads();

    const int h = tid >> 5;
    const int hoff = h * HD;

    // ---- Fused pass: each K/V row loaded ONCE, used for both queries.
    // 8 lanes/candidate; cg group handles contiguous pair {2cg, 2cg+1}.
    // Split-reduce: low half-lanes carry query A, high half carry query B.
    // unroll 2: straight-line 16-candidate body lets ptxas interleave the
    // second half's LDGs under the first half's shfl/ex2 chain.
    const int sub = lane & 7;
    const int cg  = lane >> 3;
    const bool loH = (lane & 4) == 0;
    const float4 q4A = ((const float4*)qsA)[h*8 + sub];
    const float4 q4B = ((const float4*)qsB)[h*8 + sub];
    const float* kh = k + hoff + sub*4;
    const float* vh = v + hoff + sub*4;

    float sumA = 0.f, sumB = 0.f;
    float4 aA = make_float4(0.f,0.f,0.f,0.f);
    float4 aB = make_float4(0.f,0.f,0.f,0.f);

    const int m8 = (m + 7) & ~7;
    #pragma unroll 2
    for (int c0 = 0; c0 < m8; c0 += 8) {
        const int2 ci = *(const int2*)&cand[c0 + 2*cg];
        const int o1 = ci.x & ~255, f1 = ci.x & 3;
        const int o2 = ci.y & ~255, f2 = ci.y & 3;
        float4 k1 = *(const float4*)(kh + o1);
        float4 k2 = *(const float4*)(kh + o2);
        float4 v1 = *(const float4*)(vh + o1);
        float4 v2 = *(const float4*)(vh + o2);
        float d1A = k1.x*q4A.x + k1.y*q4A.y + k1.z*q4A.z + k1.w*q4A.w;
        float d1B = k1.x*q4B.x + k1.y*q4B.y + k1.z*q4B.z + k1.w*q4B.w;
        float d2A = k2.x*q4A.x + k2.y*q4A.y + k2.z*q4A.z + k2.w*q4A.w;
        float d2B = k2.x*q4B.x + k2.y*q4B.y + k2.z*q4B.z + k2.w*q4B.w;
        // fold opposite-query halves via xor4, then 2-level reduce (both
        // queries simultaneously: low lanes sum A, high lanes sum B)
        float r1 = (loH ? d1A : d1B) + __shfl_xor_sync(0xffffffffu, loH ? d1B : d1A, 4);
        float r2 = (loH ? d2A : d2B) + __shfl_xor_sync(0xffffffffu, loH ? d2B : d2A, 4);
        r1 += __shfl_xor_sync(0xffffffffu, r1, 1);
        r2 += __shfl_xor_sync(0xffffffffu, r2, 1);
        r1 += __shfl_xor_sync(0xffffffffu, r1, 2);
        r2 += __shfl_xor_sync(0xffffffffu, r2, 2);
        // one exp per chain: low lanes produce eA, high lanes eB
        const bool ok1 = loH ? (f1 & 1) : (f1 & 2);
        const bool ok2 = loH ? (f2 & 1) : (f2 & 2);
        float e1 = ok1 ? ex2(r1) : 0.f;
        float e2 = ok2 ? ex2(r2) : 0.f;
        // broadcast the opposite half's e
        float e1o = __shfl_xor_sync(0xffffffffu, e1, 4);
        float e2o = __shfl_xor_sync(0xffffffffu, e2, 4);
        float e1A = loH ? e1 : e1o,  e1B = loH ? e1o : e1;
        float e2A = loH ? e2 : e2o,  e2B = loH ? e2o : e2;
        sumA += e1A + e2A;
        sumB += e1B + e2B;
        aA.x += e1A*v1.x + e2A*v2.x;  aB.x += e1B*v1.x + e2B*v2.x;
        aA.y += e1A*v1.y + e2A*v2.y;  aB.y += e1B*v1.y + e2B*v2.y;
        aA.z += e1A*v1.z + e2A*v2.z;  aB.z += e1B*v1.z + e2B*v2.z;
        aA.w += e1A*v1.w + e2A*v2.w;  aB.w += e1B*v1.w + e2B*v2.w;
    }

    // reduce across the 4 cg groups (disjoint candidate subsets)
    #pragma unroll
    for (int o = 8; o <= 16; o <<= 1) {
        sumA += __shfl_xor_sync(0xffffffffu, sumA, o);
        sumB += __shfl_xor_sync(0xffffffffu, sumB, o);
        aA.x += __shfl_xor_sync(0xffffffffu, aA.x, o);
        aA.y += __shfl_xor_sync(0xffffffffu, aA.y, o);
        aA.z += __shfl_xor_sync(0xffffffffu, aA.z, o);
        aA.w += __shfl_xor_sync(0xffffffffu, aA.w, o);
        aB.x += __shfl_xor_sync(0xffffffffu, aB.x, o);
        aB.y += __shfl_xor_sync(0xffffffffu, aB.y, o);
        aB.z += __shfl_xor_sync(0xffffffffu, aB.z, o);
        aB.w += __shfl_xor_sync(0xffffffffu, aB.w, o);
    }

    const float invA = (sumA > 0.f) ? (1.f / sumA) : 0.f;
    const float invB = (sumB > 0.f) ? (1.f / sumB) : 0.f;
    if (cg == 0) {
        float4 o4 = make_float4(aA.x*invA, aA.y*invA, aA.z*invA, aA.w*invA);
        *(float4*)(out + (size_t)lA*QS + hoff + sub*4) = o4;
    } else if (cg == 1) {
        float4 o4 = make_float4(aB.x*invB, aB.y*invB, aB.z*invB, aB.w*invB);
        *(float4*)(out + (size_t)lB*QS + hoff + sub*4) = o4;
    }
}

extern "C" void kernel_launch(void* const* d_in, const int* in_sizes, int n_in,
                              void* d_out, int out_size) {
    const float* q  = (const float*)d_in[0];
    const float* k  = (const float*)d_in[1];
    const float* v  = (const float*)d_in[2];
    const float* K0 = (const float*)d_in[3];
    const float* K1 = (const float*)d_in[4];
    const float* R  = (const float*)d_in[5];
    const float* t  = (const float*)d_in[6];
    float* out = (float*)d_out;
    one2many_attn_kernel<<<SS/2, 256>>>(q, k, v, K0, K1, R, t, out);
}

// round 16
// speedup vs baseline: 1.0390x; 1.0195x over previous
#include <cuda_runtime.h>
#include <math.h>

#define HH 32
#define WW 40
#define SS 1280
#define NH 8
#define HD 32
#define CAP 384
#define CAPP 384
#define QS 256   // NH*HD

// ---- strict IEEE fp32 helpers (no compiler contraction possible) ----
#define FMUL(a,b)    __fmul_rn((a),(b))
#define FADD(a,b)    __fadd_rn((a),(b))
#define FSUB(a,b)    __fsub_rn((a),(b))
#define FDIV(a,b)    __fdiv_rn((a),(b))

__device__ __forceinline__ float ex2(float x) {
    float r;
    asm("ex2.approx.f32 %0, %1;" : "=f"(r) : "f"(x));
    return r;
}

// 3x3 fp32 matmul: multiply then reduce-add, NO fma, k ascending
// (bit-exact match to the reference pipeline — do not modify).
__device__ __forceinline__ void mm3(const float A[9], const float B[9], float C[9]) {
    #pragma unroll
    for (int i = 0; i < 3; i++)
        #pragma unroll
        for (int j = 0; j < 3; j++) {
            float p0 = FMUL(A[i*3+0], B[0*3+j]);
            float p1 = FMUL(A[i*3+1], B[1*3+j]);
            float p2 = FMUL(A[i*3+2], B[2*3+j]);
            C[i*3+j] = FADD(FADD(p0, p1), p2);
        }
}

__global__ __launch_bounds__(256, 5)
void one2many_attn_kernel(
    const float* __restrict__ q, const float* __restrict__ k, const float* __restrict__ v,
    const float* __restrict__ K0, const float* __restrict__ K1,
    const float* __restrict__ R,  const float* __restrict__ t,
    float* __restrict__ out)
{
    __shared__ float qsA[QS], qsB[QS];
    __shared__ __align__(16) int cand[CAP + 8];   // both-valid: plain offsets s*256
    __shared__ int candP[CAPP + 4];               // partial: (s*256)|flags
    __shared__ int   cnt, cntP;
    __shared__ float geo[4];                 // slopeA, iceptA, slopeB, iceptB
    __shared__ int   gmode[2];

    const int pr  = blockIdx.x;
    const int lA  = 2*pr, lB = 2*pr + 1;     // same row (WW even)
    const int tid = threadIdx.x;
    const int lane = tid & 31;

    // ---- inline geometry (bit-exact; F computed once, two line evals)
    if (tid == 0) {
        auto inv_ut = [](const float* K, float ik[9]) {
            float i00 = FDIV(1.0f, K[0]);
            float i11 = FDIV(1.0f, K[4]);
            float i22 = FDIV(1.0f, K[8]);
            float x1  = FDIV(FMUL(-K[5], i22), K[4]);
            float x0  = FDIV(FMUL(-K[2], i22), K[0]);
            ik[0]=i00; ik[1]=0.f; ik[2]=x0;
            ik[3]=0.f; ik[4]=i11; ik[5]=x1;
            ik[6]=0.f; ik[7]=0.f; ik[8]=i22;
        };
        float ik0[9], ik1[9], rr[9];
        inv_ut(K0, ik0);
        inv_ut(K1, ik1);
        #pragma unroll
        for (int i = 0; i < 9; i++) rr[i] = R[i];

        const float t0 = t[0], t1 = t[1], t2 = t[2];
        const float sk[9] = { 0.f, -t2,  t1,
                              t2,  0.f, -t0,
                             -t1,  t0,  0.f };
        float ik1T[9];
        #pragma unroll
        for (int i = 0; i < 3; i++)
            #pragma unroll
            for (int j = 0; j < 3; j++) ik1T[i*3+j] = ik1[j*3+i];

        float T1[9], T2[9], F[9];
        mm3(ik1T, sk, T1);
        mm3(T1, rr, T2);
        mm3(T2, ik0, F);

        #pragma unroll
        for (int e = 0; e < 2; e++) {
            const int l = lA + e;
            const float x = (float)(l % WW), y = (float)(l / WW);
            float a = FADD(FADD(FMUL(F[0], x), FMUL(F[1], y)), F[2]);
            float b = FADD(FADD(FMUL(F[3], x), FMUL(F[4], y)), F[5]);
            float c = FADD(FADD(FMUL(F[6], x), FMUL(F[7], y)), F[8]);
            const bool mode = fabsf(b) > fabsf(a);
            const float denom = mode ? b : a;
            geo[2*e+0] = FDIV(-(mode ? a : b), denom);
            geo[2*e+1] = FDIV(-c, denom);
            gmode[e]   = mode ? 1 : 0;
        }
        cnt = 0; cntP = 0;
    }
    // q pre-scaled by 1/sqrt(32)*log2(e): dots feed ex2 directly.
    const float QSCALE = 0.25505393f;   // 0.17677669529663687 * 1.4426950408889634
    qsA[tid] = q[(size_t)lA * QS + tid] * QSCALE;
    qsB[tid] = q[(size_t)lB * QS + tid] * QSCALE;
    __syncthreads();

    const float slopeA = geo[0], iceptA = geo[1];
    const float slopeB = geo[2], iceptB = geo[3];
    const bool  modeA  = gmode[0] != 0, modeB = gmode[1] != 0;

    // ---- candidate enumeration, two segments:
    //   cand : candidates inside BOTH queries' bands (no flags)  [~96%]
    //   candP: boundary candidates valid for one query (with flags)
    // Comparisons are the EXACT strict-fp32 tests of the reference pipeline
    // for each query independently -> identical membership bits.
    if (modeA == modeB) {
        const bool mode = modeA;
        const int indepN = mode ? WW : HH;
        const int depmax = mode ? HH : WW;
        if (tid < indepN) {
            float fi = (float)tid;
            float cvA = FADD(FMUL(slopeA, fi), iceptA);
            float hiA = FADD(cvA, 2.0f), loA = FSUB(cvA, 2.0f);
            float cvB = FADD(FMUL(slopeB, fi), iceptB);
            float hiB = FADD(cvB, 2.0f), loB = FSUB(cvB, 2.0f);
            int d0 = (int)floorf(fminf(loA, loB)); if (d0 < 0) d0 = 0;
            int d1 = (int)ceilf (fmaxf(hiA, hiB)); if (d1 > depmax-1) d1 = depmax-1;
            int hits3[6]; int n3 = 0;
            int hitsP[6]; int nP = 0;
            for (int d = d0; d <= d1; d++) {
                float fd = (float)d;
                int fl = ((fd < hiA && fd > loA) ? 1 : 0)
                       | ((fd < hiB && fd > loB) ? 2 : 0);
                int s = mode ? d*WW + tid : tid*WW + d;
                if (s && fl == 3)      { if (n3 < 6) hits3[n3++] = s << 8; }
                else if (s && fl)      { if (nP < 6) hitsP[nP++] = (s << 8) | fl; }
            }
            if (n3) {
                int p = atomicAdd(&cnt, n3);
                for (int j = 0; j < n3; j++)
                    if (p + j < CAP) cand[p + j] = hits3[j];
            }
            if (nP) {
                int p = atomicAdd(&cntP, nP);
                for (int j = 0; j < nP; j++)
                    if (p + j < CAPP) candP[p + j] = hitsP[j];
            }
        }
    } else {
        // rare fallback: append each query's set separately to the partial
        // list (no dedup; exact).
        #pragma unroll
        for (int e = 0; e < 2; e++) {
            const float slope = (e == 0) ? slopeA : slopeB;
            const float icept = (e == 0) ? iceptA : iceptB;
            const bool  mode  = (e == 0) ? modeA  : modeB;
            const int indepN = mode ? WW : HH;
            const int depmax = mode ? HH : WW;
            if (tid < indepN) {
                float fi = (float)tid;
                float cv = FADD(FMUL(slope, fi), icept);
                float hi = FADD(cv, 2.0f), lo = FSUB(cv, 2.0f);
                int d0 = (int)floorf(lo); if (d0 < 0) d0 = 0;
                int d1 = (int)ceilf(hi);  if (d1 > depmax-1) d1 = depmax-1;
                int hits[6]; int nh = 0;
                for (int d = d0; d <= d1 && nh < 6; d++) {
                    float fd = (float)d;
                    if (fd < hi && fd > lo) {
                        int s = mode ? d*WW + tid : tid*WW + d;
                        if (s) hits[nh++] = (s << 8) | (1 << e);
                    }
                }
                if (nh) {
                    int p = atomicAdd(&cntP, nh);
                    for (int j = 0; j < nh; j++)
                        if (p + j < CAPP) candP[p + j] = hits[j];
                }
            }
        }
    }
    __syncthreads();

    // Move the main-segment residue (m mod 8) into the partial list (flags=3)
    // so the hot loop has an exact trip count with zero masking.
    const int m_main = min(cnt, CAP);
    if (tid < (m_main & 7)) {
        int e = cand[(m_main & ~7) + tid];
        int p = atomicAdd(&cntP, 1);
        if (p < CAPP) candP[p] = e | 3;
    }
    __syncthreads();

    const int m3 = m_main & ~7;
    const int mp = min(cntP, CAPP);

    const int h = tid >> 5;
    const int hoff = h * HD;

    // ---- Fused pass: each K/V row loaded ONCE, used for both queries.
    // 8 lanes/candidate; cg group handles contiguous pair {2cg, 2cg+1}.
    // Split-reduce: low half-lanes carry query A, high half carry query B.
    const int sub = lane & 7;
    const int cg  = lane >> 3;
    const bool loH = (lane & 4) == 0;
    const float4 q4A = ((const float4*)qsA)[h*8 + sub];
    const float4 q4B = ((const float4*)qsB)[h*8 + sub];
    const float* kh = k + hoff + sub*4;
    const float* vh = v + hoff + sub*4;

    float sumA = 0.f, sumB = 0.f;
    float4 aA = make_float4(0.f,0.f,0.f,0.f);
    float4 aB = make_float4(0.f,0.f,0.f,0.f);

    // hot loop: both-valid candidates, no flags, no masking, exact trips
    #pragma unroll 2
    for (int c0 = 0; c0 < m3; c0 += 8) {
        const int2 ci = *(const int2*)&cand[c0 + 2*cg];
        float4 k1 = *(const float4*)(kh + ci.x);
        float4 k2 = *(const float4*)(kh + ci.y);
        float4 v1 = *(const float4*)(vh + ci.x);
        float4 v2 = *(const float4*)(vh + ci.y);
        float d1A = k1.x*q4A.x + k1.y*q4A.y + k1.z*q4A.z + k1.w*q4A.w;
        float d1B = k1.x*q4B.x + k1.y*q4B.y + k1.z*q4B.z + k1.w*q4B.w;
        float d2A = k2.x*q4A.x + k2.y*q4A.y + k2.z*q4A.z + k2.w*q4A.w;
        float d2B = k2.x*q4B.x + k2.y*q4B.y + k2.z*q4B.z + k2.w*q4B.w;
        float r1 = (loH ? d1A : d1B) + __shfl_xor_sync(0xffffffffu, loH ? d1B : d1A, 4);
        float r2 = (loH ? d2A : d2B) + __shfl_xor_sync(0xffffffffu, loH ? d2B : d2A, 4);
        r1 += __shfl_xor_sync(0xffffffffu, r1, 1);
        r2 += __shfl_xor_sync(0xffffffffu, r2, 1);
        r1 += __shfl_xor_sync(0xffffffffu, r1, 2);
        r2 += __shfl_xor_sync(0xffffffffu, r2, 2);
        float e1 = ex2(r1);              // unconditional: both queries valid
        float e2 = ex2(r2);
        float e1o = __shfl_xor_sync(0xffffffffu, e1, 4);
        float e2o = __shfl_xor_sync(0xffffffffu, e2, 4);
        float e1A = loH ? e1 : e1o,  e1B = loH ? e1o : e1;
        float e2A = loH ? e2 : e2o,  e2B = loH ? e2o : e2;
        sumA += e1A + e2A;
        sumB += e1B + e2B;
        aA.x += e1A*v1.x + e2A*v2.x;  aB.x += e1B*v1.x + e2B*v2.x;
        aA.y += e1A*v1.y + e2A*v2.y;  aB.y += e1B*v1.y + e2B*v2.y;
        aA.z += e1A*v1.z + e2A*v2.z;  aB.z += e1B*v1.z + e2B*v2.z;
        aA.w += e1A*v1.w + e2A*v2.w;  aB.w += e1B*v1.w + e2B*v2.w;
    }

    // partial loop: boundary candidates + residue, flagged & masked (short)
    const int cPad = (mp + 3) & ~3;
    for (int c = cg; c < cPad; c += 4) {
        const bool vld = (c < mp);
        const int e = candP[vld ? c : 0];
        const int o = e & ~255;
        const int f = vld ? (e & 3) : 0;
        float4 k1 = *(const float4*)(kh + o);
        float4 v1 = *(const float4*)(vh + o);
        float dA = k1.x*q4A.x + k1.y*q4A.y + k1.z*q4A.z + k1.w*q4A.w;
        float dB = k1.x*q4B.x + k1.y*q4B.y + k1.z*q4B.z + k1.w*q4B.w;
        float r = (loH ? dA : dB) + __shfl_xor_sync(0xffffffffu, loH ? dB : dA, 4);
        r += __shfl_xor_sync(0xffffffffu, r, 1);
        r += __shfl_xor_sync(0xffffffffu, r, 2);
        const bool ok = loH ? (f & 1) : (f & 2);
        float e1 = ok ? ex2(r) : 0.f;
        float e1o = __shfl_xor_sync(0xffffffffu, e1, 4);
        float eA = loH ? e1 : e1o,  eB = loH ? e1o : e1;
        sumA += eA;  sumB += eB;
        aA.x += eA*v1.x;  aB.x += eB*v1.x;
        aA.y += eA*v1.y;  aB.y += eB*v1.y;
        aA.z += eA*v1.z;  aB.z += eB*v1.z;
        aA.w += eA*v1.w;  aB.w += eB*v1.w;
    }

    // reduce across the 4 cg groups (disjoint candidate subsets)
    #pragma unroll
    for (int o = 8; o <= 16; o <<= 1) {
        sumA += __shfl_xor_sync(0xffffffffu, sumA, o);
        sumB += __shfl_xor_sync(0xffffffffu, sumB, o);
        aA.x += __shfl_xor_sync(0xffffffffu, aA.x, o);
        aA.y += __shfl_xor_sync(0xffffffffu, aA.y, o);
        aA.z += __shfl_xor_sync(0xffffffffu, aA.z, o);
        aA.w += __shfl_xor_sync(0xffffffffu, aA.w, o);
        aB.x += __shfl_xor_sync(0xffffffffu, aB.x, o);
        aB.y += __shfl_xor_sync(0xffffffffu, aB.y, o);
        aB.z += __shfl_xor_sync(0xffffffffu, aB.z, o);
        aB.w += __shfl_xor_sync(0xffffffffu, aB.w, o);
    }

    const float invA = (sumA > 0.f) ? __fdividef(1.f, sumA) : 0.f;
    const float invB = (sumB > 0.f) ? __fdividef(1.f, sumB) : 0.f;
    if (cg == 0) {
        float4 o4 = make_float4(aA.x*invA, aA.y*invA, aA.z*invA, aA.w*invA);
        *(float4*)(out + (size_t)lA*QS + hoff + sub*4) = o4;
    } else if (cg == 1) {
        float4 o4 = make_float4(aB.x*invB, aB.y*invB, aB.z*invB, aB.w*invB);
        *(float4*)(out + (size_t)lB*QS + hoff + sub*4) = o4;
    }
}

extern "C" void kernel_launch(void* const* d_in, const int* in_sizes, int n_in,
                              void* d_out, int out_size) {
    const float* q  = (const float*)d_in[0];
    const float* k  = (const float*)d_in[1];
    const float* v  = (const float*)d_in[2];
    const float* K0 = (const float*)d_in[3];
    const float* K1 = (const float*)d_in[4];
    const float* R  = (const float*)d_in[5];
    const float* t  = (const float*)d_in[6];
    float* out = (float*)d_out;
    one2many_attn_kernel<<<SS/2, 256>>>(q, k, v, K0, K1, R, t, out);
}